// round 2
// baseline (speedup 1.0000x reference)
#include <cuda_runtime.h>
#include <math.h>

#define B_   8
#define S_   4096
#define D_   256
#define SEG_ 128
#define E_   32
#define MASKVAL (-3.402823466e38f)

#define SEQ_STRIDE 260
#define TRS_STRIDE 33
#define SC_STRIDE  129

// Scratch: transposed weight (L2-resident, reused by all 256 CTAs) + fix flags.
__device__ float g_wT[D_ * D_];
__device__ int   g_fix[E_];

// ---------------------------------------------------------------------------
// Kernel 1: transpose w (w[m][d] -> wT[d][m]) and zero fix flags.
// ---------------------------------------------------------------------------
__global__ void prep_kernel(const float* __restrict__ w) {
    int idx = blockIdx.x * 256 + threadIdx.x;   // 65536 threads
    int m = idx >> 8;
    int d = idx & 255;
    g_wT[d * D_ + m] = w[idx];
    if (idx < E_) g_fix[idx] = 0;
}

// ---------------------------------------------------------------------------
// Kernel 2: fix[e] = any_{b,l} all_k (mask[b, e*128+l, e*128+k] == MASKVAL)
// ---------------------------------------------------------------------------
__global__ void fix_kernel(const float* __restrict__ mask) {
    int e = blockIdx.x;
    int warp = threadIdx.x >> 5, lane = threadIdx.x & 31;
    int found = 0;
    for (int r = warp; r < B_ * SEG_; r += 8) {
        int b = r >> 7, l = r & 127;
        const float* row = mask + ((size_t)b * S_ + (size_t)e * SEG_ + l) * S_
                                + (size_t)e * SEG_;
        int allm = 1;
        #pragma unroll
        for (int k = 0; k < 4; k++)
            if (row[lane + 32 * k] != MASKVAL) allm = 0;
        if (__all_sync(0xffffffffu, allm)) { found = 1; break; }   // warp-uniform
    }
    if (found && lane == 0) atomicOr(&g_fix[e], 1);
}

// ---------------------------------------------------------------------------
// Kernel 3: main. One CTA per (e, b) segment. 256 threads.
// ---------------------------------------------------------------------------
__global__ void __launch_bounds__(256, 1)
main_kernel(const float* __restrict__ hidden,
            const float* __restrict__ mask,
            const float* __restrict__ bvec,
            float* __restrict__ out)
{
    extern __shared__ float sm[];
    float* seq_s  = sm;                             // [128][260]
    float* trsfT  = seq_s + SEG_ * SEQ_STRIDE;      // [256][33]  (trsf transposed)
    float* sc_s   = trsfT + D_ * TRS_STRIDE;        // [32][129]
    float* pool_s = sc_s + 32 * SC_STRIDE;          // [4][256]
    float* b_s    = pool_s + 4 * D_;                // [256]

    const int t = threadIdx.x;
    const int e = blockIdx.x, b = blockIdx.y;

    const float* seq_g = hidden + ((size_t)b * S_ + (size_t)e * SEG_) * D_;

    // Load segment tile (128x256 fp32) into smem, float4, conflict-free.
    for (int i = t; i < SEG_ * D_ / 4; i += 256) {
        int l = i >> 6;
        int d = (i & 63) << 2;
        float4 v = *(const float4*)(seq_g + l * D_ + d);
        *(float4*)(seq_s + l * SEQ_STRIDE + d) = v;
    }
    b_s[t] = bvec[t];
    const int fixe = g_fix[e];

    // Per-thread tile mappings.
    const int mA = (t & 31) << 3;   const int lA = (t >> 5) << 2;   // A: 4l x 8m
    const int lB = (t & 7)  << 2;   const int kB = (t >> 3) << 2;   // B: 4l x 4k
    const int dC = (t & 63) << 2;   const int lC = (t >> 6) << 3;   // C: 8l x 4d

    float pool0 = -3.4e38f, pool1 = -3.4e38f, pool2 = -3.4e38f, pool3 = -3.4e38f;

    __syncthreads();

    for (int lt = 0; lt < 4; lt++) {
        const int l0 = lt << 5;

        // ---- Phase A: trsf tile = tanh(seq[l0:l0+32] @ wT + b), stored transposed
        {
            float acc[4][8];
            #pragma unroll
            for (int i = 0; i < 4; i++)
                #pragma unroll
                for (int j = 0; j < 8; j++) acc[i][j] = 0.0f;

            const float* wp  = g_wT + mA;
            const float* sq0 = seq_s + (l0 + lA) * SEQ_STRIDE;
            #pragma unroll 4
            for (int d = 0; d < D_; d++) {
                float4 w0 = *(const float4*)(wp + d * D_);
                float4 w1 = *(const float4*)(wp + d * D_ + 4);
                float wv[8] = {w0.x, w0.y, w0.z, w0.w, w1.x, w1.y, w1.z, w1.w};
                float sv[4];
                #pragma unroll
                for (int i = 0; i < 4; i++) sv[i] = sq0[i * SEQ_STRIDE + d];
                #pragma unroll
                for (int i = 0; i < 4; i++)
                    #pragma unroll
                    for (int j = 0; j < 8; j++)
                        acc[i][j] += sv[i] * wv[j];
            }
            #pragma unroll
            for (int j = 0; j < 8; j++) {
                float bj = b_s[mA + j];
                #pragma unroll
                for (int i = 0; i < 4; i++)
                    trsfT[(mA + j) * TRS_STRIDE + lA + i] = tanhf(acc[i][j] + bj);
            }
        }
        __syncthreads();

        // ---- Phase B: scores[l][k] = trsf[l] . seq[k]  (+ mask block) ----
        {
            float acc[4][4];
            #pragma unroll
            for (int i = 0; i < 4; i++)
                #pragma unroll
                for (int j = 0; j < 4; j++) acc[i][j] = 0.0f;

            #pragma unroll 4
            for (int m = 0; m < D_; m++) {
                float tv[4], sv[4];
                #pragma unroll
                for (int i = 0; i < 4; i++) tv[i] = trsfT[m * TRS_STRIDE + lB + i];
                #pragma unroll
                for (int j = 0; j < 4; j++) sv[j] = seq_s[(kB + j) * SEQ_STRIDE + m];
                #pragma unroll
                for (int i = 0; i < 4; i++)
                    #pragma unroll
                    for (int j = 0; j < 4; j++)
                        acc[i][j] += tv[i] * sv[j];
            }
            #pragma unroll
            for (int i = 0; i < 4; i++) {
                int gl = l0 + lB + i;   // row within segment
                const float* mr = mask + ((size_t)b * S_ + (size_t)e * SEG_ + gl) * S_
                                       + (size_t)e * SEG_ + kB;
                #pragma unroll
                for (int j = 0; j < 4; j++) {
                    float mv = mr[j];
                    if (fixe && gl == 0) mv = 0.0f;
                    sc_s[(lB + i) * SC_STRIDE + kB + j] = acc[i][j] + mv;
                }
            }
        }
        __syncthreads();

        // ---- Softmax over k (rows of sc_s), warp per 4 rows ----
        {
            int warp = t >> 5, lane = t & 31;
            #pragma unroll
            for (int i = 0; i < 4; i++) {
                float* row = sc_s + ((warp << 2) + i) * SC_STRIDE;
                float v0 = row[lane], v1 = row[lane + 32],
                      v2 = row[lane + 64], v3 = row[lane + 96];
                float mx = fmaxf(fmaxf(v0, v1), fmaxf(v2, v3));
                #pragma unroll
                for (int o = 16; o > 0; o >>= 1)
                    mx = fmaxf(mx, __shfl_xor_sync(0xffffffffu, mx, o));
                v0 = expf(v0 - mx); v1 = expf(v1 - mx);
                v2 = expf(v2 - mx); v3 = expf(v3 - mx);
                float sum = v0 + v1 + v2 + v3;
                #pragma unroll
                for (int o = 16; o > 0; o >>= 1)
                    sum += __shfl_xor_sync(0xffffffffu, sum, o);
                float inv = 1.0f / sum;
                row[lane]      = v0 * inv; row[lane + 32] = v1 * inv;
                row[lane + 64] = v2 * inv; row[lane + 96] = v3 * inv;
            }
        }
        __syncthreads();

        // ---- Phase C: ctx[l][d] = attn[l] . seq[:,d]; fold max-pool over l ----
        {
            float acc[8][4];
            #pragma unroll
            for (int i = 0; i < 8; i++)
                #pragma unroll
                for (int j = 0; j < 4; j++) acc[i][j] = 0.0f;

            #pragma unroll 2
            for (int k = 0; k < SEG_; k++) {
                float4 s4 = *(const float4*)(seq_s + k * SEQ_STRIDE + dC);
                float sv[4] = {s4.x, s4.y, s4.z, s4.w};
                float av[8];
                #pragma unroll
                for (int i = 0; i < 8; i++) av[i] = sc_s[(lC + i) * SC_STRIDE + k];
                #pragma unroll
                for (int i = 0; i < 8; i++)
                    #pragma unroll
                    for (int j = 0; j < 4; j++)
                        acc[i][j] += av[i] * sv[j];
            }
            #pragma unroll
            for (int i = 0; i < 8; i++) {
                pool0 = fmaxf(pool0, acc[i][0]);
                pool1 = fmaxf(pool1, acc[i][1]);
                pool2 = fmaxf(pool2, acc[i][2]);
                pool3 = fmaxf(pool3, acc[i][3]);
            }
        }
        __syncthreads();
    }

    // Combine pooled max across the 4 l-groups.
    {
        int grp = t >> 6;
        pool_s[grp * D_ + dC + 0] = pool0;
        pool_s[grp * D_ + dC + 1] = pool1;
        pool_s[grp * D_ + dC + 2] = pool2;
        pool_s[grp * D_ + dC + 3] = pool3;
    }
    __syncthreads();

    float* outP = out + ((size_t)b * E_ + e) * D_;
    if (t < 64) {
        #pragma unroll
        for (int j = 0; j < 4; j++) {
            int d = (t << 2) + j;
            float m0 = fmaxf(pool_s[d],          pool_s[D_ + d]);
            float m1 = fmaxf(pool_s[2 * D_ + d], pool_s[3 * D_ + d]);
            outP[d] = fmaxf(m0, m1);
        }
    }

    // new_mask[b][e][s] = (s/128 == e)
    float* nm = out + (size_t)B_ * E_ * D_ + ((size_t)b * E_ + e) * S_;
    for (int s = t; s < S_; s += 256)
        nm[s] = ((s >> 7) == e) ? 1.0f : 0.0f;
}

// ---------------------------------------------------------------------------
extern "C" void kernel_launch(void* const* d_in, const int* in_sizes, int n_in,
                              void* d_out, int out_size) {
    const float* hidden = (const float*)d_in[0];
    const float* mask   = (const float*)d_in[1];
    const float* w      = (const float*)d_in[2];
    const float* bvec   = (const float*)d_in[3];
    float* out = (float*)d_out;
    (void)in_sizes; (void)n_in; (void)out_size;

    prep_kernel<<<256, 256>>>(w);
    fix_kernel<<<E_, 256>>>(mask);

    size_t smem = (size_t)(SEG_ * SEQ_STRIDE + D_ * TRS_STRIDE + 32 * SC_STRIDE
                           + 4 * D_ + D_) * sizeof(float);
    cudaFuncSetAttribute(main_kernel,
                         cudaFuncAttributeMaxDynamicSharedMemorySize, (int)smem);
    main_kernel<<<dim3(E_, B_), 256, smem>>>(hidden, mask, bvec, out);
}

// round 3
// speedup vs baseline: 2.3982x; 2.3982x over previous
#include <cuda_runtime.h>
#include <cuda_bf16.h>
#include <math.h>

#define B_   8
#define S_   4096
#define D_   256
#define SEG_ 128
#define E_   32
#define MASKVAL (-3.402823466e38f)

// strides in halves (16-bit units)
#define SEQ_ST 264
#define TRS_ST 264
#define ATT_ST 136
#define WB_ST  24
#define SC_ST  132   // floats

// smem byte offsets
#define OFF_SEQH 0
#define OFF_SEQL (OFF_SEQH + 128*SEQ_ST*2)
#define OFF_TRSH (OFF_SEQL + 128*SEQ_ST*2)
#define OFF_TRSL (OFF_TRSH + 32*TRS_ST*2)
#define OFF_ATTH (OFF_TRSL + 32*TRS_ST*2)
#define OFF_ATTL (OFF_ATTH + 32*ATT_ST*2)
#define OFF_WBH  (OFF_ATTL + 32*ATT_ST*2)
#define OFF_WBL  (OFF_WBH + 256*WB_ST*2)
#define OFF_SC   (OFF_WBL + 256*WB_ST*2)
#define OFF_BIAS (OFF_SC + 32*SC_ST*4)
#define SMEM_TOT (OFF_BIAS + 256*4)     // 228,864 B

// w packed per 16-wide k-chunk: [kc][m][kk], hi and lo bf16 splits
__device__ __nv_bfloat16 g_wh[16*256*16];
__device__ __nv_bfloat16 g_wl[16*256*16];
__device__ int g_fix[E_];

// ---------------------------------------------------------------------------
__global__ void prep_kernel(const float* __restrict__ w) {
    int idx = blockIdx.x * 256 + threadIdx.x;   // 65536
    int m = idx >> 8, d = idx & 255;
    float v = w[idx];
    __nv_bfloat16 h = __float2bfloat16(v);
    __nv_bfloat16 l = __float2bfloat16(v - __bfloat162float(h));
    int kc = d >> 4, kk = d & 15;
    int o = (kc * 256 + m) * 16 + kk;
    g_wh[o] = h; g_wl[o] = l;
    if (idx < E_) g_fix[idx] = 0;
}

// ---------------------------------------------------------------------------
__global__ void fix_kernel(const float* __restrict__ mask) {
    int e = blockIdx.x;
    int warp = threadIdx.x >> 5, lane = threadIdx.x & 31;
    int found = 0;
    for (int r = warp; r < B_ * SEG_; r += 8) {
        int b = r >> 7, l = r & 127;
        const float* row = mask + ((size_t)b * S_ + (size_t)e * SEG_ + l) * S_
                                + (size_t)e * SEG_;
        int allm = 1;
        #pragma unroll
        for (int k = 0; k < 4; k++)
            if (row[lane + 32 * k] != MASKVAL) allm = 0;
        if (__all_sync(0xffffffffu, allm)) { found = 1; break; }
    }
    if (found && lane == 0) atomicOr(&g_fix[e], 1);
}

// ---------------------------------------------------------------------------
__device__ __forceinline__ void ldsm4(unsigned a, unsigned& r0, unsigned& r1,
                                      unsigned& r2, unsigned& r3) {
    asm volatile("ldmatrix.sync.aligned.m8n8.x4.shared.b16 {%0,%1,%2,%3},[%4];"
                 : "=r"(r0), "=r"(r1), "=r"(r2), "=r"(r3) : "r"(a));
}
__device__ __forceinline__ void ldsm4t(unsigned a, unsigned& r0, unsigned& r1,
                                       unsigned& r2, unsigned& r3) {
    asm volatile("ldmatrix.sync.aligned.m8n8.x4.trans.shared.b16 {%0,%1,%2,%3},[%4];"
                 : "=r"(r0), "=r"(r1), "=r"(r2), "=r"(r3) : "r"(a));
}
__device__ __forceinline__ void mma16816(float* c, unsigned a0, unsigned a1,
                                         unsigned a2, unsigned a3,
                                         unsigned b0, unsigned b1) {
    asm volatile(
        "mma.sync.aligned.m16n8k16.row.col.f32.bf16.bf16.f32 "
        "{%0,%1,%2,%3},{%4,%5,%6,%7},{%8,%9},{%0,%1,%2,%3};"
        : "+f"(c[0]), "+f"(c[1]), "+f"(c[2]), "+f"(c[3])
        : "r"(a0), "r"(a1), "r"(a2), "r"(a3), "r"(b0), "r"(b1));
}
__device__ __forceinline__ __nv_bfloat162 split_hi2(float x, float y) {
    __nv_bfloat162 r; r.x = __float2bfloat16(x); r.y = __float2bfloat16(y); return r;
}
__device__ __forceinline__ __nv_bfloat162 split_lo2(float x, float y,
                                                    __nv_bfloat162 h) {
    __nv_bfloat162 r;
    r.x = __float2bfloat16(x - __bfloat162float(h.x));
    r.y = __float2bfloat16(y - __bfloat162float(h.y));
    return r;
}

// ---------------------------------------------------------------------------
__global__ void __launch_bounds__(256, 1)
main_kernel(const float* __restrict__ hidden,
            const float* __restrict__ maskp,
            const float* __restrict__ bvec,
            float* __restrict__ out)
{
    extern __shared__ char smc[];
    const unsigned sb = (unsigned)__cvta_generic_to_shared(smc);

    __nv_bfloat16* seqh = (__nv_bfloat16*)(smc + OFF_SEQH);
    __nv_bfloat16* seql = (__nv_bfloat16*)(smc + OFF_SEQL);
    __nv_bfloat16* trsh = (__nv_bfloat16*)(smc + OFF_TRSH);
    __nv_bfloat16* trsl = (__nv_bfloat16*)(smc + OFF_TRSL);
    __nv_bfloat16* atth = (__nv_bfloat16*)(smc + OFF_ATTH);
    __nv_bfloat16* attl = (__nv_bfloat16*)(smc + OFF_ATTL);
    float*         sc   = (float*)(smc + OFF_SC);
    float*         bias = (float*)(smc + OFF_BIAS);

    const int t = threadIdx.x;
    const int lane = t & 31, wi = t >> 5;
    const int wr = wi >> 2, wc = wi & 3;
    const int rg = lane >> 2, c2 = (lane & 3) * 2;
    const int e = blockIdx.x, bb = blockIdx.y;

    const float* seq_g = hidden + ((size_t)bb * S_ + (size_t)e * SEG_) * D_;

    // ---- load seq tile, split into bf16 hi/lo ----
    for (int i = t; i < SEG_ * D_ / 4; i += 256) {
        int l = i >> 6, d = (i & 63) << 2;
        float4 v = *(const float4*)(seq_g + l * D_ + d);
        __nv_bfloat162 h0 = split_hi2(v.x, v.y), h1 = split_hi2(v.z, v.w);
        __nv_bfloat162 l0 = split_lo2(v.x, v.y, h0), l1 = split_lo2(v.z, v.w, h1);
        *(__nv_bfloat162*)(seqh + l * SEQ_ST + d)     = h0;
        *(__nv_bfloat162*)(seqh + l * SEQ_ST + d + 2) = h1;
        *(__nv_bfloat162*)(seql + l * SEQ_ST + d)     = l0;
        *(__nv_bfloat162*)(seql + l * SEQ_ST + d + 2) = l1;
    }
    bias[t] = bvec[t];
    const int fixe = g_fix[e];

    // ldmatrix address helpers (canonical m16n8k16 row.col maps)
    auto adrA = [&](unsigned off, int st, int r0, int k0) -> unsigned {
        int r = r0 + (lane & 7) + ((lane >> 3) & 1) * 8;
        int c = k0 + ((lane >> 4) & 1) * 8;
        return sb + off + (unsigned)((r * st + c) * 2);
    };
    auto adrB = [&](unsigned off, int st, int n0, int k0) -> unsigned {
        int r = n0 + (lane & 7) + ((lane >> 4) & 1) * 8;
        int c = k0 + ((lane >> 3) & 1) * 8;
        return sb + off + (unsigned)((r * st + c) * 2);
    };
    auto adrBt = [&](unsigned off, int st, int k0, int d0) -> unsigned {
        int r = k0 + (lane & 7) + ((lane >> 3) & 1) * 8;
        int c = d0 + ((lane >> 4) & 1) * 8;
        return sb + off + (unsigned)((r * st + c) * 2);
    };

    float poolE[8], poolO[8];
    #pragma unroll
    for (int i = 0; i < 8; i++) { poolE[i] = -3.4e38f; poolO[i] = -3.4e38f; }

    __syncthreads();

    for (int lt = 0; lt < 4; lt++) {
        const int l0 = lt * 32;

        // ============ Phase A: trsf = tanh(seq @ w^T + b) ============
        float accA[8][4];
        #pragma unroll
        for (int i = 0; i < 8; i++)
            #pragma unroll
            for (int j = 0; j < 4; j++) accA[i][j] = 0.0f;

        uint4 ph0, ph1, pl0, pl1;
        {
            const uint4* gh = (const uint4*)(g_wh + t * 16);
            const uint4* gl = (const uint4*)(g_wl + t * 16);
            ph0 = gh[0]; ph1 = gh[1]; pl0 = gl[0]; pl1 = gl[1];
        }
        for (int kc = 0; kc < 16; kc++) {
            __syncthreads();
            *(uint4*)(smc + OFF_WBH + t * WB_ST * 2)      = ph0;
            *(uint4*)(smc + OFF_WBH + t * WB_ST * 2 + 16) = ph1;
            *(uint4*)(smc + OFF_WBL + t * WB_ST * 2)      = pl0;
            *(uint4*)(smc + OFF_WBL + t * WB_ST * 2 + 16) = pl1;
            if (kc < 15) {
                const uint4* gh = (const uint4*)(g_wh + (kc + 1) * 4096 + t * 16);
                const uint4* gl = (const uint4*)(g_wl + (kc + 1) * 4096 + t * 16);
                ph0 = gh[0]; ph1 = gh[1]; pl0 = gl[0]; pl1 = gl[1];
            }
            __syncthreads();

            unsigned ah0, ah1, ah2, ah3, al0, al1, al2, al3;
            ldsm4(adrA(OFF_SEQH, SEQ_ST, l0 + wr * 16, kc * 16), ah0, ah1, ah2, ah3);
            ldsm4(adrA(OFF_SEQL, SEQ_ST, l0 + wr * 16, kc * 16), al0, al1, al2, al3);
            #pragma unroll
            for (int p = 0; p < 4; p++) {
                unsigned bh0, bh1, bh2, bh3, bl0_, bl1_, bl2_, bl3_;
                ldsm4(adrB(OFF_WBH, WB_ST, wc * 64 + p * 16, 0), bh0, bh1, bh2, bh3);
                ldsm4(adrB(OFF_WBL, WB_ST, wc * 64 + p * 16, 0), bl0_, bl1_, bl2_, bl3_);
                mma16816(accA[2*p],   ah0, ah1, ah2, ah3, bh0, bh1);
                mma16816(accA[2*p],   ah0, ah1, ah2, ah3, bl0_, bl1_);
                mma16816(accA[2*p],   al0, al1, al2, al3, bh0, bh1);
                mma16816(accA[2*p+1], ah0, ah1, ah2, ah3, bh2, bh3);
                mma16816(accA[2*p+1], ah0, ah1, ah2, ah3, bl2_, bl3_);
                mma16816(accA[2*p+1], al0, al1, al2, al3, bh2, bh3);
            }
        }
        // epilogue A: bias + tanh -> trsf hi/lo
        #pragma unroll
        for (int nt = 0; nt < 8; nt++) {
            int m0 = wc * 64 + nt * 8 + c2;
            float bv0 = bias[m0], bv1 = bias[m0 + 1];
            float v00 = tanhf(accA[nt][0] + bv0), v01 = tanhf(accA[nt][1] + bv1);
            float v10 = tanhf(accA[nt][2] + bv0), v11 = tanhf(accA[nt][3] + bv1);
            __nv_bfloat162 h0 = split_hi2(v00, v01), L0 = split_lo2(v00, v01, h0);
            __nv_bfloat162 h1 = split_hi2(v10, v11), L1 = split_lo2(v10, v11, h1);
            int r0 = wr * 16 + rg, r1 = r0 + 8;
            *(__nv_bfloat162*)(trsh + r0 * TRS_ST + m0) = h0;
            *(__nv_bfloat162*)(trsl + r0 * TRS_ST + m0) = L0;
            *(__nv_bfloat162*)(trsh + r1 * TRS_ST + m0) = h1;
            *(__nv_bfloat162*)(trsl + r1 * TRS_ST + m0) = L1;
        }
        __syncthreads();

        // ============ Phase B: scores = trsf @ seq^T (+ mask) ============
        float accB[4][4];
        #pragma unroll
        for (int i = 0; i < 4; i++)
            #pragma unroll
            for (int j = 0; j < 4; j++) accB[i][j] = 0.0f;

        for (int kc = 0; kc < 16; kc++) {
            unsigned ah0, ah1, ah2, ah3, al0, al1, al2, al3;
            ldsm4(adrA(OFF_TRSH, TRS_ST, wr * 16, kc * 16), ah0, ah1, ah2, ah3);
            ldsm4(adrA(OFF_TRSL, TRS_ST, wr * 16, kc * 16), al0, al1, al2, al3);
            #pragma unroll
            for (int p = 0; p < 2; p++) {
                unsigned bh0, bh1, bh2, bh3, bl0_, bl1_, bl2_, bl3_;
                ldsm4(adrB(OFF_SEQH, SEQ_ST, wc * 32 + p * 16, kc * 16),
                      bh0, bh1, bh2, bh3);
                ldsm4(adrB(OFF_SEQL, SEQ_ST, wc * 32 + p * 16, kc * 16),
                      bl0_, bl1_, bl2_, bl3_);
                mma16816(accB[2*p],   ah0, ah1, ah2, ah3, bh0, bh1);
                mma16816(accB[2*p],   ah0, ah1, ah2, ah3, bl0_, bl1_);
                mma16816(accB[2*p],   al0, al1, al2, al3, bh0, bh1);
                mma16816(accB[2*p+1], ah0, ah1, ah2, ah3, bh2, bh3);
                mma16816(accB[2*p+1], ah0, ah1, ah2, ah3, bl2_, bl3_);
                mma16816(accB[2*p+1], al0, al1, al2, al3, bh2, bh3);
            }
        }
        // epilogue B: + mask block, store fp32 scores
        #pragma unroll
        for (int nt = 0; nt < 4; nt++) {
            int k2 = wc * 32 + nt * 8 + c2;
            int gl0 = l0 + wr * 16 + rg;
            const float* mr0 = maskp + ((size_t)(bb * S_ + e * SEG_ + gl0)) * S_
                                     + (size_t)e * SEG_ + k2;
            float2 m0v = *(const float2*)mr0;
            float2 m1v = *(const float2*)(mr0 + (size_t)8 * S_);
            if (fixe && gl0 == 0) { m0v.x = 0.0f; m0v.y = 0.0f; }
            int r0 = wr * 16 + rg, r1 = r0 + 8;
            sc[r0 * SC_ST + k2]     = accB[nt][0] + m0v.x;
            sc[r0 * SC_ST + k2 + 1] = accB[nt][1] + m0v.y;
            sc[r1 * SC_ST + k2]     = accB[nt][2] + m1v.x;
            sc[r1 * SC_ST + k2 + 1] = accB[nt][3] + m1v.y;
        }
        __syncthreads();

        // ============ softmax + bf16 split of attn ============
        #pragma unroll
        for (int i = 0; i < 4; i++) {
            int row = wi * 4 + i;
            float* r = sc + row * SC_ST;
            float v0 = r[lane], v1 = r[lane + 32], v2 = r[lane + 64], v3 = r[lane + 96];
            float mx = fmaxf(fmaxf(v0, v1), fmaxf(v2, v3));
            #pragma unroll
            for (int o = 16; o > 0; o >>= 1)
                mx = fmaxf(mx, __shfl_xor_sync(0xffffffffu, mx, o));
            v0 = expf(v0 - mx); v1 = expf(v1 - mx);
            v2 = expf(v2 - mx); v3 = expf(v3 - mx);
            float sum = v0 + v1 + v2 + v3;
            #pragma unroll
            for (int o = 16; o > 0; o >>= 1)
                sum += __shfl_xor_sync(0xffffffffu, sum, o);
            float inv = 1.0f / sum;
            v0 *= inv; v1 *= inv; v2 *= inv; v3 *= inv;
            float vs[4] = {v0, v1, v2, v3};
            #pragma unroll
            for (int q = 0; q < 4; q++) {
                __nv_bfloat16 h = __float2bfloat16(vs[q]);
                __nv_bfloat16 l = __float2bfloat16(vs[q] - __bfloat162float(h));
                atth[row * ATT_ST + lane + 32 * q] = h;
                attl[row * ATT_ST + lane + 32 * q] = l;
            }
        }
        __syncthreads();

        // ============ Phase C: ctx = attn @ seq, fold max-pool ============
        float accC[8][4];
        #pragma unroll
        for (int i = 0; i < 8; i++)
            #pragma unroll
            for (int j = 0; j < 4; j++) accC[i][j] = 0.0f;

        for (int kc = 0; kc < 8; kc++) {
            unsigned ah0, ah1, ah2, ah3, al0, al1, al2, al3;
            ldsm4(adrA(OFF_ATTH, ATT_ST, wr * 16, kc * 16), ah0, ah1, ah2, ah3);
            ldsm4(adrA(OFF_ATTL, ATT_ST, wr * 16, kc * 16), al0, al1, al2, al3);
            #pragma unroll
            for (int p = 0; p < 4; p++) {
                unsigned bh0, bh1, bh2, bh3, bl0_, bl1_, bl2_, bl3_;
                ldsm4t(adrBt(OFF_SEQH, SEQ_ST, kc * 16, wc * 64 + p * 16),
                       bh0, bh1, bh2, bh3);
                ldsm4t(adrBt(OFF_SEQL, SEQ_ST, kc * 16, wc * 64 + p * 16),
                       bl0_, bl1_, bl2_, bl3_);
                mma16816(accC[2*p],   ah0, ah1, ah2, ah3, bh0, bh1);
                mma16816(accC[2*p],   ah0, ah1, ah2, ah3, bl0_, bl1_);
                mma16816(accC[2*p],   al0, al1, al2, al3, bh0, bh1);
                mma16816(accC[2*p+1], ah0, ah1, ah2, ah3, bh2, bh3);
                mma16816(accC[2*p+1], ah0, ah1, ah2, ah3, bl2_, bl3_);
                mma16816(accC[2*p+1], al0, al1, al2, al3, bh2, bh3);
            }
        }
        #pragma unroll
        for (int nt = 0; nt < 8; nt++) {
            poolE[nt] = fmaxf(poolE[nt], fmaxf(accC[nt][0], accC[nt][2]));
            poolO[nt] = fmaxf(poolO[nt], fmaxf(accC[nt][1], accC[nt][3]));
        }
        __syncthreads();
    }

    // ---- final pool reduction (alias wbuf region) ----
    float* pool_sm = (float*)(smc + OFF_WBH);   // 16 x 256 floats
    int slot = wr * 8 + rg;
    #pragma unroll
    for (int nt = 0; nt < 8; nt++) {
        int col = wc * 64 + nt * 8 + c2;
        pool_sm[slot * 256 + col]     = poolE[nt];
        pool_sm[slot * 256 + col + 1] = poolO[nt];
    }
    __syncthreads();

    float mx = -3.4e38f;
    #pragma unroll
    for (int s = 0; s < 16; s++) mx = fmaxf(mx, pool_sm[s * 256 + t]);
    out[((size_t)bb * E_ + e) * D_ + t] = mx;

    // new_mask[b][e][s] = (s/128 == e)
    float* nm = out + (size_t)B_ * E_ * D_ + ((size_t)bb * E_ + e) * S_;
    for (int s = t; s < S_; s += 256)
        nm[s] = ((s >> 7) == e) ? 1.0f : 0.0f;
}

// ---------------------------------------------------------------------------
extern "C" void kernel_launch(void* const* d_in, const int* in_sizes, int n_in,
                              void* d_out, int out_size) {
    const float* hidden = (const float*)d_in[0];
    const float* mask   = (const float*)d_in[1];
    const float* w      = (const float*)d_in[2];
    const float* bvec   = (const float*)d_in[3];
    float* out = (float*)d_out;
    (void)in_sizes; (void)n_in; (void)out_size;

    prep_kernel<<<256, 256>>>(w);
    fix_kernel<<<E_, 256>>>(mask);

    cudaFuncSetAttribute(main_kernel,
                         cudaFuncAttributeMaxDynamicSharedMemorySize, SMEM_TOT);
    main_kernel<<<dim3(E_, B_), 256, SMEM_TOT>>>(hidden, mask, bvec, out);
}